// round 1
// baseline (speedup 1.0000x reference)
#include <cuda_runtime.h>
#include <math.h>

#define BATCH 4
#define T_SEQ 2048
#define NH 12
#define DMODEL 768
#define DH 64
#define M_ROWS (BATCH * T_SEQ)          // 8192
#define QKV_N (3 * DMODEL)              // 2304

// Scratch (static device globals — allocation-free per harness rules)
__device__ float g_qkv[(size_t)M_ROWS * QKV_N];   // [8192, 2304]
__device__ float g_y[(size_t)M_ROWS * DMODEL];    // [8192, 768]

// ---------------------------------------------------------------------------
// SGEMM with bias: C[M,N] = A[M,K] @ B[K,N] + bias[N]
// Block tile 128x128, K-step 16, 256 threads, 8x8 per-thread register tile.
// Assumes M%128==0, N%128==0, K%16==0, all pointers 16B-aligned (true here).
// ---------------------------------------------------------------------------
__global__ __launch_bounds__(256) void sgemm_bias_kernel(
    const float* __restrict__ A, const float* __restrict__ B,
    const float* __restrict__ bias, float* __restrict__ C,
    int M, int N, int K)
{
    __shared__ float As[16][128];   // transposed A tile: As[k][m]
    __shared__ float Bs[16][128];   // Bs[k][n]

    const int tid = threadIdx.x;
    const int tx = tid & 15;        // 0..15 -> N direction
    const int ty = tid >> 4;        // 0..15 -> M direction
    const int bx = blockIdx.x;      // N tile
    const int by = blockIdx.y;      // M tile

    const float* Ablk = A + (size_t)by * 128 * K;
    const float* Bblk = B + (size_t)bx * 128;

    float acc[8][8];
    #pragma unroll
    for (int i = 0; i < 8; i++)
        #pragma unroll
        for (int j = 0; j < 8; j++) acc[i][j] = 0.0f;

    for (int k0 = 0; k0 < K; k0 += 16) {
        // Load A tile: 128x16 floats = 512 float4, 2 per thread (transpose into As)
        #pragma unroll
        for (int it = 0; it < 2; it++) {
            int idx = tid + it * 256;
            int row = idx >> 2;           // 0..127
            int kc  = (idx & 3) << 2;     // 0,4,8,12
            float4 v = *(const float4*)(Ablk + (size_t)row * K + k0 + kc);
            As[kc + 0][row] = v.x;
            As[kc + 1][row] = v.y;
            As[kc + 2][row] = v.z;
            As[kc + 3][row] = v.w;
        }
        // Load B tile: 16x128 floats = 512 float4, 2 per thread
        #pragma unroll
        for (int it = 0; it < 2; it++) {
            int idx = tid + it * 256;
            int row = idx >> 5;           // 0..15
            int c4  = (idx & 31) << 2;    // 0..124
            *(float4*)&Bs[row][c4] =
                *(const float4*)(Bblk + (size_t)(k0 + row) * N + c4);
        }
        __syncthreads();

        #pragma unroll
        for (int kk = 0; kk < 16; kk++) {
            float ra[8], rb[8];
            *(float4*)&ra[0] = *(const float4*)&As[kk][ty * 8];
            *(float4*)&ra[4] = *(const float4*)&As[kk][ty * 8 + 4];
            *(float4*)&rb[0] = *(const float4*)&Bs[kk][tx * 8];
            *(float4*)&rb[4] = *(const float4*)&Bs[kk][tx * 8 + 4];
            #pragma unroll
            for (int i = 0; i < 8; i++)
                #pragma unroll
                for (int j = 0; j < 8; j++)
                    acc[i][j] = fmaf(ra[i], rb[j], acc[i][j]);
        }
        __syncthreads();
    }

    // Epilogue: add bias, store
    const int col0 = bx * 128 + tx * 8;
    float bv[8];
    #pragma unroll
    for (int j = 0; j < 8; j++) bv[j] = bias[col0 + j];

    #pragma unroll
    for (int i = 0; i < 8; i++) {
        int row = by * 128 + ty * 8 + i;
        float* cp = C + (size_t)row * N + col0;
        float4 o0, o1;
        o0.x = acc[i][0] + bv[0]; o0.y = acc[i][1] + bv[1];
        o0.z = acc[i][2] + bv[2]; o0.w = acc[i][3] + bv[3];
        o1.x = acc[i][4] + bv[4]; o1.y = acc[i][5] + bv[5];
        o1.z = acc[i][6] + bv[6]; o1.w = acc[i][7] + bv[7];
        *(float4*)cp = o0;
        *(float4*)(cp + 4) = o1;
    }
}

// ---------------------------------------------------------------------------
// Flash attention (causal), fp32.
// Grid: (T/64, B*H). Block: 256 threads (16x16).
// Q tile: 64 rows x 64. K/V tiles: 32 rows x 64.
// Thread (ty,tx): S rows ty*4+i (i<4), S cols tx*2+j (j<2), O cols tx*4+j (j<4).
// ---------------------------------------------------------------------------
__global__ __launch_bounds__(256) void flash_attn_kernel(
    const float* __restrict__ qkv, float* __restrict__ y)
{
    __shared__ float Qs[64][65];
    __shared__ float Ks[32][65];
    __shared__ float Vs[32][65];
    __shared__ float Ps[64][33];

    const int tid = threadIdx.x;
    const int tx = tid & 15;
    const int ty = tid >> 4;
    const int qt = blockIdx.x;          // q tile index (rows qt*64 .. +63)
    const int bh = blockIdx.y;
    const int b = bh / NH;
    const int h = bh % NH;
    const float scale = 0.125f;         // 1/sqrt(64)

    const size_t row_stride = QKV_N;
    const size_t base = (size_t)b * T_SEQ * row_stride;
    const int qoff = h * DH;
    const int koff = DMODEL + h * DH;
    const int voff = 2 * DMODEL + h * DH;

    // Load Q tile: 64x64 = 1024 float4, 4 per thread
    #pragma unroll
    for (int it = 0; it < 4; it++) {
        int idx = tid + it * 256;
        int r  = idx >> 4;             // 0..63
        int c4 = (idx & 15) << 2;      // 0..60
        float4 v = *(const float4*)(qkv + base + (size_t)(qt * 64 + r) * row_stride + qoff + c4);
        Qs[r][c4 + 0] = v.x; Qs[r][c4 + 1] = v.y;
        Qs[r][c4 + 2] = v.z; Qs[r][c4 + 3] = v.w;
    }

    float m_i[4], l_i[4], acc[4][4];
    #pragma unroll
    for (int i = 0; i < 4; i++) {
        m_i[i] = -1e30f;
        l_i[i] = 0.0f;
        #pragma unroll
        for (int j = 0; j < 4; j++) acc[i][j] = 0.0f;
    }

    const int nkt = 2 * qt + 2;         // causal: K tiles of 32 rows
    for (int kt = 0; kt < nkt; kt++) {
        __syncthreads();  // protect Ks/Vs from previous iteration's readers
        // Load K,V tiles: 32x64 each = 512 float4 each, 2+2 per thread
        #pragma unroll
        for (int it = 0; it < 2; it++) {
            int idx = tid + it * 256;
            int r  = idx >> 4;          // 0..31
            int c4 = (idx & 15) << 2;
            const float* src = qkv + base + (size_t)(kt * 32 + r) * row_stride;
            float4 kv = *(const float4*)(src + koff + c4);
            Ks[r][c4 + 0] = kv.x; Ks[r][c4 + 1] = kv.y;
            Ks[r][c4 + 2] = kv.z; Ks[r][c4 + 3] = kv.w;
            float4 vv = *(const float4*)(src + voff + c4);
            Vs[r][c4 + 0] = vv.x; Vs[r][c4 + 1] = vv.y;
            Vs[r][c4 + 2] = vv.z; Vs[r][c4 + 3] = vv.w;
        }
        __syncthreads();

        // S = scale * Q K^T  (rows ty*4+i, cols tx*2+j)
        float s[4][2];
        #pragma unroll
        for (int i = 0; i < 4; i++) { s[i][0] = 0.0f; s[i][1] = 0.0f; }
        #pragma unroll 8
        for (int d = 0; d < 64; d++) {
            float k0 = Ks[tx * 2 + 0][d];
            float k1 = Ks[tx * 2 + 1][d];
            #pragma unroll
            for (int i = 0; i < 4; i++) {
                float qv = Qs[ty * 4 + i][d];
                s[i][0] = fmaf(qv, k0, s[i][0]);
                s[i][1] = fmaf(qv, k1, s[i][1]);
            }
        }

        const bool need_mask = (kt >= 2 * qt);
        #pragma unroll
        for (int i = 0; i < 4; i++) {
            #pragma unroll
            for (int j = 0; j < 2; j++) {
                s[i][j] *= scale;
                if (need_mask) {
                    int gr = qt * 64 + ty * 4 + i;
                    int gc = kt * 32 + tx * 2 + j;
                    if (gc > gr) s[i][j] = -1e30f;
                }
            }
        }

        // Online softmax per row (reduction across the 16-lane tx group)
        #pragma unroll
        for (int i = 0; i < 4; i++) {
            float tm = fmaxf(s[i][0], s[i][1]);
            #pragma unroll
            for (int off = 1; off < 16; off <<= 1)
                tm = fmaxf(tm, __shfl_xor_sync(0xffffffffu, tm, off));
            float mn = fmaxf(m_i[i], tm);
            float corr = __expf(m_i[i] - mn);
            float p0 = __expf(s[i][0] - mn);
            float p1 = __expf(s[i][1] - mn);
            float rs = p0 + p1;
            #pragma unroll
            for (int off = 1; off < 16; off <<= 1)
                rs += __shfl_xor_sync(0xffffffffu, rs, off);
            l_i[i] = l_i[i] * corr + rs;
            m_i[i] = mn;
            #pragma unroll
            for (int j = 0; j < 4; j++) acc[i][j] *= corr;
            Ps[ty * 4 + i][tx * 2 + 0] = p0;
            Ps[ty * 4 + i][tx * 2 + 1] = p1;
        }
        __syncthreads();

        // O += P @ V   (O cols tx*4+j)
        #pragma unroll 8
        for (int kc = 0; kc < 32; kc++) {
            float vv[4];
            #pragma unroll
            for (int j = 0; j < 4; j++) vv[j] = Vs[kc][tx * 4 + j];
            #pragma unroll
            for (int i = 0; i < 4; i++) {
                float p = Ps[ty * 4 + i][kc];
                #pragma unroll
                for (int j = 0; j < 4; j++)
                    acc[i][j] = fmaf(p, vv[j], acc[i][j]);
            }
        }
    }

    // Write out: y[b*T + r][h*64 + tx*4 + j]
    #pragma unroll
    for (int i = 0; i < 4; i++) {
        float inv = 1.0f / l_i[i];
        int r = qt * 64 + ty * 4 + i;
        float4 o;
        o.x = acc[i][0] * inv;
        o.y = acc[i][1] * inv;
        o.z = acc[i][2] * inv;
        o.w = acc[i][3] * inv;
        *(float4*)(y + ((size_t)b * T_SEQ + r) * DMODEL + h * DH + tx * 4) = o;
    }
}

// ---------------------------------------------------------------------------
extern "C" void kernel_launch(void* const* d_in, const int* in_sizes, int n_in,
                              void* d_out, int out_size)
{
    const float* x      = (const float*)d_in[0];
    const float* w_attn = (const float*)d_in[1];
    const float* b_attn = (const float*)d_in[2];
    const float* w_proj = (const float*)d_in[3];
    const float* b_proj = (const float*)d_in[4];
    float* out = (float*)d_out;

    float* qkv_ptr = nullptr;
    float* y_ptr = nullptr;
    cudaGetSymbolAddress((void**)&qkv_ptr, g_qkv);
    cudaGetSymbolAddress((void**)&y_ptr, g_y);

    // 1) QKV GEMM: [8192,768] @ [768,2304] + bias
    {
        dim3 grid(QKV_N / 128, M_ROWS / 128);   // (18, 64)
        sgemm_bias_kernel<<<grid, 256>>>(x, w_attn, b_attn, qkv_ptr,
                                         M_ROWS, QKV_N, DMODEL);
    }
    // 2) Causal flash attention
    {
        dim3 grid(T_SEQ / 64, BATCH * NH);      // (32, 48)
        flash_attn_kernel<<<grid, 256>>>(qkv_ptr, y_ptr);
    }
    // 3) Output projection: [8192,768] @ [768,768] + bias
    {
        dim3 grid(DMODEL / 128, M_ROWS / 128);  // (6, 64)
        sgemm_bias_kernel<<<grid, 256>>>(y_ptr, w_proj, b_proj, out,
                                         M_ROWS, DMODEL, DMODEL);
    }
}

// round 4
// speedup vs baseline: 1.2995x; 1.2995x over previous
#include <cuda_runtime.h>
#include <cuda_bf16.h>
#include <cstdint>
#include <math.h>

#define BATCH 4
#define T_SEQ 2048
#define NH 12
#define DMODEL 768
#define DH 64
#define M_ROWS (BATCH * T_SEQ)          // 8192
#define QKV_N (3 * DMODEL)              // 2304
#define GK DMODEL                       // GEMM K = 768
#define KCHUNK 64
#define LDS_PAD 72                      // smem row stride in bf16 (144 B)

// ------------------------- scratch (static, allocation-free) ---------------
__device__ float g_qkv[(size_t)M_ROWS * QKV_N];   // fp32 [8192, 2304]
__device__ float g_y[(size_t)M_ROWS * DMODEL];    // fp32 [8192, 768]
__device__ __nv_bfloat16 g_xh[(size_t)M_ROWS * DMODEL];
__device__ __nv_bfloat16 g_xl[(size_t)M_ROWS * DMODEL];
__device__ __nv_bfloat16 g_yh[(size_t)M_ROWS * DMODEL];
__device__ __nv_bfloat16 g_yl[(size_t)M_ROWS * DMODEL];
__device__ __nv_bfloat16 g_wah[(size_t)QKV_N * DMODEL];  // w_attn^T [2304,768]
__device__ __nv_bfloat16 g_wal[(size_t)QKV_N * DMODEL];
__device__ __nv_bfloat16 g_wph[(size_t)DMODEL * DMODEL]; // w_proj^T [768,768]
__device__ __nv_bfloat16 g_wpl[(size_t)DMODEL * DMODEL];

// ------------------------- warp MMA helpers (baseline PTX, sm_80+) ---------
__device__ __forceinline__ uint32_t smem_u32(const void* p) {
    uint32_t a;
    asm("{ .reg .u64 t; cvta.to.shared.u64 t, %1; cvt.u32.u64 %0, t; }" : "=r"(a) : "l"(p));
    return a;
}

__device__ __forceinline__ void ldsm_x4(uint32_t& r0, uint32_t& r1,
                                        uint32_t& r2, uint32_t& r3, uint32_t addr) {
    asm volatile("ldmatrix.sync.aligned.m8n8.x4.shared.b16 {%0,%1,%2,%3}, [%4];"
                 : "=r"(r0), "=r"(r1), "=r"(r2), "=r"(r3) : "r"(addr));
}

__device__ __forceinline__ void mma_bf16(float* c, const uint32_t* a,
                                         uint32_t b0, uint32_t b1) {
    asm volatile(
        "mma.sync.aligned.m16n8k16.row.col.f32.bf16.bf16.f32 "
        "{%0,%1,%2,%3}, {%4,%5,%6,%7}, {%8,%9}, {%0,%1,%2,%3};"
        : "+f"(c[0]), "+f"(c[1]), "+f"(c[2]), "+f"(c[3])
        : "r"(a[0]), "r"(a[1]), "r"(a[2]), "r"(a[3]), "r"(b0), "r"(b1));
}

// ---------------------------------------------------------------------------
// HMMA GEMM, bf16x3 emulating fp32: C[M,N] = Ah*Bh + Al*Bh + Ah*Bl + bias
// A* row-major [M,768] bf16; B* = W^T row-major [N,768] bf16; C fp32 [M,N].
// CTA tile 128x128, K-chunk 64, 256 threads = 8 warps (4M x 2N), warp 32x64.
// ---------------------------------------------------------------------------
__global__ __launch_bounds__(256, 2) void mma_gemm_kernel(
    const __nv_bfloat16* __restrict__ Ah, const __nv_bfloat16* __restrict__ Al,
    const __nv_bfloat16* __restrict__ Bh, const __nv_bfloat16* __restrict__ Bl,
    const float* __restrict__ bias, float* __restrict__ C, int N)
{
    __shared__ __nv_bfloat16 Asm[128 * LDS_PAD];
    __shared__ __nv_bfloat16 Bsm[128 * LDS_PAD];

    const int tid  = threadIdx.x;
    const int wid  = tid >> 5;
    const int lane = tid & 31;
    const int m0 = blockIdx.y * 128;
    const int n0 = blockIdx.x * 128;
    const int warp_m = (wid >> 1) * 32;   // 0,32,64,96
    const int warp_n = (wid & 1) * 64;    // 0,64

    const uint32_t As_base = smem_u32(Asm);
    const uint32_t Bs_base = smem_u32(Bsm);

    // ldmatrix row indices (constant per thread)
    const int a_row = (lane & 15);                                  // within 16-row block
    const int a_coff = (lane >> 4) * 8;                             // 0 or 8 (k)
    const int b_row = (lane & 7) + ((lane >> 3) & 1) * 8;           // within 16-row block
    const int b_coff = ((lane >> 4) & 1) * 8;                       // 0 or 8 (k)

    float acc[2][8][4];
    #pragma unroll
    for (int mi = 0; mi < 2; mi++)
        #pragma unroll
        for (int nj = 0; nj < 8; nj++)
            #pragma unroll
            for (int q = 0; q < 4; q++) acc[mi][nj][q] = 0.0f;

    #pragma unroll 1
    for (int pass = 0; pass < 3; ++pass) {
        const __nv_bfloat16* Asrc = (pass == 1) ? Al : Ah;
        const __nv_bfloat16* Bsrc = (pass == 2) ? Bl : Bh;
        #pragma unroll 1
        for (int kc = 0; kc < GK; kc += KCHUNK) {
            __syncthreads();
            // Load A,B tiles: 128 rows x 64 bf16 each; 4 uint4 per thread per tile
            #pragma unroll
            for (int it = 0; it < 4; it++) {
                int idx = tid + it * 256;
                int row = idx >> 3;            // 0..127
                int g   = idx & 7;             // 16B granule
                *(uint4*)(Asm + row * LDS_PAD + g * 8) =
                    *(const uint4*)(Asrc + (size_t)(m0 + row) * GK + kc + g * 8);
                *(uint4*)(Bsm + row * LDS_PAD + g * 8) =
                    *(const uint4*)(Bsrc + (size_t)(n0 + row) * GK + kc + g * 8);
            }
            __syncthreads();

            #pragma unroll
            for (int ks = 0; ks < 4; ks++) {
                const int k0 = ks * 16;
                uint32_t ra[2][4];
                #pragma unroll
                for (int mi = 0; mi < 2; mi++) {
                    uint32_t addr = As_base +
                        ((warp_m + mi * 16 + a_row) * LDS_PAD + k0 + a_coff) * 2;
                    ldsm_x4(ra[mi][0], ra[mi][1], ra[mi][2], ra[mi][3], addr);
                }
                uint32_t rb[4][4];
                #pragma unroll
                for (int nb = 0; nb < 4; nb++) {
                    uint32_t addr = Bs_base +
                        ((warp_n + nb * 16 + b_row) * LDS_PAD + k0 + b_coff) * 2;
                    ldsm_x4(rb[nb][0], rb[nb][1], rb[nb][2], rb[nb][3], addr);
                }
                #pragma unroll
                for (int mi = 0; mi < 2; mi++)
                    #pragma unroll
                    for (int nj = 0; nj < 8; nj++) {
                        int nb = nj >> 1, lo = nj & 1;
                        mma_bf16(acc[mi][nj], ra[mi],
                                 rb[nb][lo ? 1 : 0], rb[nb][lo ? 3 : 2]);
                    }
            }
        }
    }

    // Epilogue: c-frag -> global with bias
    const int mrow = m0 + warp_m + (lane >> 2);
    const int ncol = n0 + warp_n + (lane & 3) * 2;
    #pragma unroll
    for (int mi = 0; mi < 2; mi++) {
        #pragma unroll
        for (int nj = 0; nj < 8; nj++) {
            int r = mrow + mi * 16;
            int c = ncol + nj * 8;
            float bv0 = bias[c], bv1 = bias[c + 1];
            float2 v0 = make_float2(acc[mi][nj][0] + bv0, acc[mi][nj][1] + bv1);
            float2 v1 = make_float2(acc[mi][nj][2] + bv0, acc[mi][nj][3] + bv1);
            *(float2*)(C + (size_t)r * N + c) = v0;
            *(float2*)(C + (size_t)(r + 8) * N + c) = v1;
        }
    }
}

// ---------------------------------------------------------------------------
// fp32 -> (hi, lo) bf16 split
// ---------------------------------------------------------------------------
__global__ __launch_bounds__(256) void split_kernel(
    const float* __restrict__ in, __nv_bfloat16* __restrict__ hi,
    __nv_bfloat16* __restrict__ lo, int n4)
{
    int i = blockIdx.x * blockDim.x + threadIdx.x;
    if (i >= n4) return;
    float4 v = *(const float4*)(in + (size_t)i * 4);
    __nv_bfloat16 h[4], l[4];
    float f[4] = {v.x, v.y, v.z, v.w};
    #pragma unroll
    for (int k = 0; k < 4; ++k) {
        h[k] = __float2bfloat16(f[k]);
        l[k] = __float2bfloat16(f[k] - __bfloat162float(h[k]));
    }
    *(uint2*)(hi + (size_t)i * 4) = *(uint2*)h;
    *(uint2*)(lo + (size_t)i * 4) = *(uint2*)l;
}

// ---------------------------------------------------------------------------
// W [K,N] fp32 -> W^T (hi, lo) bf16 [N,K]
// ---------------------------------------------------------------------------
__global__ __launch_bounds__(256) void split_transpose_kernel(
    const float* __restrict__ W, __nv_bfloat16* __restrict__ hiT,
    __nv_bfloat16* __restrict__ loT, int K, int N)
{
    __shared__ float tile[32][33];
    const int tx = threadIdx.x;        // 0..31
    const int ty = threadIdx.y;        // 0..7
    const int k0 = blockIdx.y * 32;
    const int n0 = blockIdx.x * 32;
    #pragma unroll
    for (int r = 0; r < 32; r += 8)
        tile[ty + r][tx] = W[(size_t)(k0 + ty + r) * N + n0 + tx];
    __syncthreads();
    #pragma unroll
    for (int r = 0; r < 32; r += 8) {
        float v = tile[tx][ty + r];
        __nv_bfloat16 h = __float2bfloat16(v);
        __nv_bfloat16 l = __float2bfloat16(v - __bfloat162float(h));
        size_t o = (size_t)(n0 + ty + r) * K + k0 + tx;
        hiT[o] = h;
        loT[o] = l;
    }
}

// ---------------------------------------------------------------------------
// Flash attention (causal), fp32 — unchanged (known-good).
// ---------------------------------------------------------------------------
__global__ __launch_bounds__(256) void flash_attn_kernel(
    const float* __restrict__ qkv, float* __restrict__ y)
{
    __shared__ float Qs[64][65];
    __shared__ float Ks[32][65];
    __shared__ float Vs[32][65];
    __shared__ float Ps[64][33];

    const int tid = threadIdx.x;
    const int tx = tid & 15;
    const int ty = tid >> 4;
    const int qt = blockIdx.x;
    const int bh = blockIdx.y;
    const int b = bh / NH;
    const int h = bh % NH;
    const float scale = 0.125f;

    const size_t row_stride = QKV_N;
    const size_t base = (size_t)b * T_SEQ * row_stride;
    const int qoff = h * DH;
    const int koff = DMODEL + h * DH;
    const int voff = 2 * DMODEL + h * DH;

    #pragma unroll
    for (int it = 0; it < 4; it++) {
        int idx = tid + it * 256;
        int r  = idx >> 4;
        int c4 = (idx & 15) << 2;
        float4 v = *(const float4*)(qkv + base + (size_t)(qt * 64 + r) * row_stride + qoff + c4);
        Qs[r][c4 + 0] = v.x; Qs[r][c4 + 1] = v.y;
        Qs[r][c4 + 2] = v.z; Qs[r][c4 + 3] = v.w;
    }

    float m_i[4], l_i[4], acc[4][4];
    #pragma unroll
    for (int i = 0; i < 4; i++) {
        m_i[i] = -1e30f;
        l_i[i] = 0.0f;
        #pragma unroll
        for (int j = 0; j < 4; j++) acc[i][j] = 0.0f;
    }

    const int nkt = 2 * qt + 2;
    for (int kt = 0; kt < nkt; kt++) {
        __syncthreads();
        #pragma unroll
        for (int it = 0; it < 2; it++) {
            int idx = tid + it * 256;
            int r  = idx >> 4;
            int c4 = (idx & 15) << 2;
            const float* src = qkv + base + (size_t)(kt * 32 + r) * row_stride;
            float4 kv = *(const float4*)(src + koff + c4);
            Ks[r][c4 + 0] = kv.x; Ks[r][c4 + 1] = kv.y;
            Ks[r][c4 + 2] = kv.z; Ks[r][c4 + 3] = kv.w;
            float4 vv = *(const float4*)(src + voff + c4);
            Vs[r][c4 + 0] = vv.x; Vs[r][c4 + 1] = vv.y;
            Vs[r][c4 + 2] = vv.z; Vs[r][c4 + 3] = vv.w;
        }
        __syncthreads();

        float s[4][2];
        #pragma unroll
        for (int i = 0; i < 4; i++) { s[i][0] = 0.0f; s[i][1] = 0.0f; }
        #pragma unroll 8
        for (int d = 0; d < 64; d++) {
            float k0 = Ks[tx * 2 + 0][d];
            float k1 = Ks[tx * 2 + 1][d];
            #pragma unroll
            for (int i = 0; i < 4; i++) {
                float qv = Qs[ty * 4 + i][d];
                s[i][0] = fmaf(qv, k0, s[i][0]);
                s[i][1] = fmaf(qv, k1, s[i][1]);
            }
        }

        const bool need_mask = (kt >= 2 * qt);
        #pragma unroll
        for (int i = 0; i < 4; i++) {
            #pragma unroll
            for (int j = 0; j < 2; j++) {
                s[i][j] *= scale;
                if (need_mask) {
                    int gr = qt * 64 + ty * 4 + i;
                    int gc = kt * 32 + tx * 2 + j;
                    if (gc > gr) s[i][j] = -1e30f;
                }
            }
        }

        #pragma unroll
        for (int i = 0; i < 4; i++) {
            float tm = fmaxf(s[i][0], s[i][1]);
            #pragma unroll
            for (int off = 1; off < 16; off <<= 1)
                tm = fmaxf(tm, __shfl_xor_sync(0xffffffffu, tm, off));
            float mn = fmaxf(m_i[i], tm);
            float corr = __expf(m_i[i] - mn);
            float p0 = __expf(s[i][0] - mn);
            float p1 = __expf(s[i][1] - mn);
            float rs = p0 + p1;
            #pragma unroll
            for (int off = 1; off < 16; off <<= 1)
                rs += __shfl_xor_sync(0xffffffffu, rs, off);
            l_i[i] = l_i[i] * corr + rs;
            m_i[i] = mn;
            #pragma unroll
            for (int j = 0; j < 4; j++) acc[i][j] *= corr;
            Ps[ty * 4 + i][tx * 2 + 0] = p0;
            Ps[ty * 4 + i][tx * 2 + 1] = p1;
        }
        __syncthreads();

        #pragma unroll 8
        for (int kc = 0; kc < 32; kc++) {
            float vv[4];
            #pragma unroll
            for (int j = 0; j < 4; j++) vv[j] = Vs[kc][tx * 4 + j];
            #pragma unroll
            for (int i = 0; i < 4; i++) {
                float p = Ps[ty * 4 + i][kc];
                #pragma unroll
                for (int j = 0; j < 4; j++)
                    acc[i][j] = fmaf(p, vv[j], acc[i][j]);
            }
        }
    }

    #pragma unroll
    for (int i = 0; i < 4; i++) {
        float inv = 1.0f / l_i[i];
        int r = qt * 64 + ty * 4 + i;
        float4 o;
        o.x = acc[i][0] * inv;
        o.y = acc[i][1] * inv;
        o.z = acc[i][2] * inv;
        o.w = acc[i][3] * inv;
        *(float4*)(y + ((size_t)b * T_SEQ + r) * DMODEL + h * DH + tx * 4) = o;
    }
}

// ---------------------------------------------------------------------------
extern "C" void kernel_launch(void* const* d_in, const int* in_sizes, int n_in,
                              void* d_out, int out_size)
{
    const float* x      = (const float*)d_in[0];
    const float* w_attn = (const float*)d_in[1];
    const float* b_attn = (const float*)d_in[2];
    const float* w_proj = (const float*)d_in[3];
    const float* b_proj = (const float*)d_in[4];
    float* out = (float*)d_out;

    float *qkv_ptr, *y_ptr;
    __nv_bfloat16 *xh, *xl, *yh, *yl, *wah, *wal, *wph, *wpl;
    cudaGetSymbolAddress((void**)&qkv_ptr, g_qkv);
    cudaGetSymbolAddress((void**)&y_ptr, g_y);
    cudaGetSymbolAddress((void**)&xh, g_xh);
    cudaGetSymbolAddress((void**)&xl, g_xl);
    cudaGetSymbolAddress((void**)&yh, g_yh);
    cudaGetSymbolAddress((void**)&yl, g_yl);
    cudaGetSymbolAddress((void**)&wah, g_wah);
    cudaGetSymbolAddress((void**)&wal, g_wal);
    cudaGetSymbolAddress((void**)&wph, g_wph);
    cudaGetSymbolAddress((void**)&wpl, g_wpl);

    // 0) conversions: x split, weights split+transpose
    {
        int n4 = (M_ROWS * DMODEL) / 4;
        split_kernel<<<(n4 + 255) / 256, 256>>>(x, xh, xl, n4);
        dim3 blk(32, 8);
        split_transpose_kernel<<<dim3(QKV_N / 32, DMODEL / 32), blk>>>(w_attn, wah, wal, DMODEL, QKV_N);
        split_transpose_kernel<<<dim3(DMODEL / 32, DMODEL / 32), blk>>>(w_proj, wph, wpl, DMODEL, DMODEL);
    }
    // 1) QKV GEMM on HMMA (bf16x3): [8192,768] @ [768,2304] + bias
    {
        dim3 grid(QKV_N / 128, M_ROWS / 128);               // (18, 64)
        mma_gemm_kernel<<<grid, 256>>>(xh, xl, wah, wal, b_attn, qkv_ptr, QKV_N);
    }
    // 2) causal flash attention (fp32)
    {
        dim3 grid(T_SEQ / 64, BATCH * NH);                  // (32, 48)
        flash_attn_kernel<<<grid, 256>>>(qkv_ptr, y_ptr);
    }
    // 3) split y, out-proj GEMM on HMMA: [8192,768] @ [768,768] + bias
    {
        int n4 = (M_ROWS * DMODEL) / 4;
        split_kernel<<<(n4 + 255) / 256, 256>>>(y_ptr, yh, yl, n4);
        dim3 grid(DMODEL / 128, M_ROWS / 128);              // (6, 64)
        mma_gemm_kernel<<<grid, 256>>>(yh, yl, wph, wpl, b_proj, out, DMODEL);
    }
}

// round 6
// speedup vs baseline: 2.6841x; 2.0654x over previous
#include <cuda_runtime.h>
#include <cuda_bf16.h>
#include <cstdint>
#include <math.h>

#define BATCH 4
#define T_SEQ 2048
#define NH 12
#define DMODEL 768
#define DH 64
#define M_ROWS (BATCH * T_SEQ)          // 8192
#define QKV_N (3 * DMODEL)              // 2304
#define GK DMODEL                       // GEMM K = 768
#define KCHUNK 64
#define LDS_PAD 72                      // smem row stride in bf16 (144 B)

// ------------------------- scratch (static, allocation-free) ---------------
__device__ __nv_bfloat16 g_qkvh[(size_t)M_ROWS * QKV_N];
__device__ __nv_bfloat16 g_qkvl[(size_t)M_ROWS * QKV_N];
__device__ __nv_bfloat16 g_xh[(size_t)M_ROWS * DMODEL];
__device__ __nv_bfloat16 g_xl[(size_t)M_ROWS * DMODEL];
__device__ __nv_bfloat16 g_yh[(size_t)M_ROWS * DMODEL];
__device__ __nv_bfloat16 g_yl[(size_t)M_ROWS * DMODEL];
__device__ __nv_bfloat16 g_wah[(size_t)QKV_N * DMODEL];  // w_attn^T [2304,768]
__device__ __nv_bfloat16 g_wal[(size_t)QKV_N * DMODEL];
__device__ __nv_bfloat16 g_wph[(size_t)DMODEL * DMODEL]; // w_proj^T [768,768]
__device__ __nv_bfloat16 g_wpl[(size_t)DMODEL * DMODEL];

// ------------------------- warp MMA helpers --------------------------------
__device__ __forceinline__ uint32_t smem_u32(const void* p) {
    uint32_t a;
    asm("{ .reg .u64 t; cvta.to.shared.u64 t, %1; cvt.u32.u64 %0, t; }" : "=r"(a) : "l"(p));
    return a;
}
__device__ __forceinline__ void ldsm_x4(uint32_t& r0, uint32_t& r1,
                                        uint32_t& r2, uint32_t& r3, uint32_t addr) {
    asm volatile("ldmatrix.sync.aligned.m8n8.x4.shared.b16 {%0,%1,%2,%3}, [%4];"
                 : "=r"(r0), "=r"(r1), "=r"(r2), "=r"(r3) : "r"(addr));
}
__device__ __forceinline__ void ldsm_x4_t(uint32_t& r0, uint32_t& r1,
                                          uint32_t& r2, uint32_t& r3, uint32_t addr) {
    asm volatile("ldmatrix.sync.aligned.m8n8.x4.trans.shared.b16 {%0,%1,%2,%3}, [%4];"
                 : "=r"(r0), "=r"(r1), "=r"(r2), "=r"(r3) : "r"(addr));
}
__device__ __forceinline__ void mma_bf16(float* c, const uint32_t* a,
                                         uint32_t b0, uint32_t b1) {
    asm volatile(
        "mma.sync.aligned.m16n8k16.row.col.f32.bf16.bf16.f32 "
        "{%0,%1,%2,%3}, {%4,%5,%6,%7}, {%8,%9}, {%0,%1,%2,%3};"
        : "+f"(c[0]), "+f"(c[1]), "+f"(c[2]), "+f"(c[3])
        : "r"(a[0]), "r"(a[1]), "r"(a[2]), "r"(a[3]), "r"(b0), "r"(b1));
}
__device__ __forceinline__ uint32_t pack_bf2(float f0, float f1) {
    __nv_bfloat162 t;
    t.x = __float2bfloat16(f0);
    t.y = __float2bfloat16(f1);
    return *(uint32_t*)&t;
}
__device__ __forceinline__ void pack_hl(float f0, float f1, uint32_t& h, uint32_t& l) {
    __nv_bfloat16 h0 = __float2bfloat16(f0), h1 = __float2bfloat16(f1);
    __nv_bfloat162 hh; hh.x = h0; hh.y = h1;
    h = *(uint32_t*)&hh;
    __nv_bfloat162 ll;
    ll.x = __float2bfloat16(f0 - __bfloat162float(h0));
    ll.y = __float2bfloat16(f1 - __bfloat162float(h1));
    l = *(uint32_t*)&ll;
}

// ---------------------------------------------------------------------------
// HMMA GEMM, bf16x3: C = Ah*Bh + Al*Bh + Ah*Bl + bias.
// Output: fp32 C (if Cl==nullptr) or bf16 hi/lo split (Ch,Cl).
// ---------------------------------------------------------------------------
__global__ __launch_bounds__(256, 2) void mma_gemm_kernel(
    const __nv_bfloat16* __restrict__ Ah, const __nv_bfloat16* __restrict__ Al,
    const __nv_bfloat16* __restrict__ Bh, const __nv_bfloat16* __restrict__ Bl,
    const float* __restrict__ bias, float* __restrict__ C,
    __nv_bfloat16* __restrict__ Ch, __nv_bfloat16* __restrict__ Cl, int N)
{
    __shared__ __nv_bfloat16 Asm[128 * LDS_PAD];
    __shared__ __nv_bfloat16 Bsm[128 * LDS_PAD];

    const int tid  = threadIdx.x;
    const int wid  = tid >> 5;
    const int lane = tid & 31;
    const int m0 = blockIdx.y * 128;
    const int n0 = blockIdx.x * 128;
    const int warp_m = (wid >> 1) * 32;
    const int warp_n = (wid & 1) * 64;

    const uint32_t As_base = smem_u32(Asm);
    const uint32_t Bs_base = smem_u32(Bsm);

    const int a_row = (lane & 15);
    const int a_coff = (lane >> 4) * 8;
    const int b_row = (lane & 7) + ((lane >> 3) & 1) * 8;
    const int b_coff = ((lane >> 4) & 1) * 8;

    float acc[2][8][4];
    #pragma unroll
    for (int mi = 0; mi < 2; mi++)
        #pragma unroll
        for (int nj = 0; nj < 8; nj++)
            #pragma unroll
            for (int q = 0; q < 4; q++) acc[mi][nj][q] = 0.0f;

    #pragma unroll 1
    for (int pass = 0; pass < 3; ++pass) {
        const __nv_bfloat16* Asrc = (pass == 1) ? Al : Ah;
        const __nv_bfloat16* Bsrc = (pass == 2) ? Bl : Bh;
        #pragma unroll 1
        for (int kc = 0; kc < GK; kc += KCHUNK) {
            __syncthreads();
            #pragma unroll
            for (int it = 0; it < 4; it++) {
                int idx = tid + it * 256;
                int row = idx >> 3;
                int g   = idx & 7;
                *(uint4*)(Asm + row * LDS_PAD + g * 8) =
                    *(const uint4*)(Asrc + (size_t)(m0 + row) * GK + kc + g * 8);
                *(uint4*)(Bsm + row * LDS_PAD + g * 8) =
                    *(const uint4*)(Bsrc + (size_t)(n0 + row) * GK + kc + g * 8);
            }
            __syncthreads();

            #pragma unroll
            for (int ks = 0; ks < 4; ks++) {
                const int k0 = ks * 16;
                uint32_t ra[2][4];
                #pragma unroll
                for (int mi = 0; mi < 2; mi++) {
                    uint32_t addr = As_base +
                        ((warp_m + mi * 16 + a_row) * LDS_PAD + k0 + a_coff) * 2;
                    ldsm_x4(ra[mi][0], ra[mi][1], ra[mi][2], ra[mi][3], addr);
                }
                uint32_t rb[4][4];
                #pragma unroll
                for (int nb = 0; nb < 4; nb++) {
                    uint32_t addr = Bs_base +
                        ((warp_n + nb * 16 + b_row) * LDS_PAD + k0 + b_coff) * 2;
                    ldsm_x4(rb[nb][0], rb[nb][1], rb[nb][2], rb[nb][3], addr);
                }
                #pragma unroll
                for (int mi = 0; mi < 2; mi++)
                    #pragma unroll
                    for (int nj = 0; nj < 8; nj++) {
                        int nb = nj >> 1, lo = nj & 1;
                        mma_bf16(acc[mi][nj], ra[mi],
                                 rb[nb][lo ? 1 : 0], rb[nb][lo ? 3 : 2]);
                    }
            }
        }
    }

    const int mrow = m0 + warp_m + (lane >> 2);
    const int ncol = n0 + warp_n + (lane & 3) * 2;
    #pragma unroll
    for (int mi = 0; mi < 2; mi++) {
        #pragma unroll
        for (int nj = 0; nj < 8; nj++) {
            int r = mrow + mi * 16;
            int c = ncol + nj * 8;
            float bv0 = bias[c], bv1 = bias[c + 1];
            float v00 = acc[mi][nj][0] + bv0, v01 = acc[mi][nj][1] + bv1;
            float v10 = acc[mi][nj][2] + bv0, v11 = acc[mi][nj][3] + bv1;
            if (Cl) {
                uint32_t h0, l0, h1, l1;
                pack_hl(v00, v01, h0, l0);
                pack_hl(v10, v11, h1, l1);
                *(uint32_t*)(Ch + (size_t)r * N + c) = h0;
                *(uint32_t*)(Cl + (size_t)r * N + c) = l0;
                *(uint32_t*)(Ch + (size_t)(r + 8) * N + c) = h1;
                *(uint32_t*)(Cl + (size_t)(r + 8) * N + c) = l1;
            } else {
                *(float2*)(C + (size_t)r * N + c) = make_float2(v00, v01);
                *(float2*)(C + (size_t)(r + 8) * N + c) = make_float2(v10, v11);
            }
        }
    }
}

// ---------------------------------------------------------------------------
// HMMA flash attention (causal), bf16x3 S and PV, fp32 softmax/accum.
// Grid (T/128, B*NH), 256 threads = 8 warps x 16 Q-rows. K/V tiles 64 rows.
// Dynamic smem: Qh|Ql (128x72 each) + Kh|Kl|Vh|Vl (64x72 each) = 73728 B.
// ---------------------------------------------------------------------------
#define AQH 0
#define AQL (128 * LDS_PAD)
#define AKH (2 * 128 * LDS_PAD)
#define AKL (AKH + 64 * LDS_PAD)
#define AVH (AKL + 64 * LDS_PAD)
#define AVL (AVH + 64 * LDS_PAD)
#define ATTN_SMEM ((AVL + 64 * LDS_PAD) * 2)

__global__ __launch_bounds__(256, 2) void mma_attn_kernel(
    const __nv_bfloat16* __restrict__ qkvh, const __nv_bfloat16* __restrict__ qkvl,
    __nv_bfloat16* __restrict__ yh, __nv_bfloat16* __restrict__ yl)
{
    extern __shared__ __nv_bfloat16 sm[];
    const int tid = threadIdx.x;
    const int wid = tid >> 5;
    const int lane = tid & 31;
    const int qt = gridDim.x - 1 - blockIdx.x;     // heavy tiles first
    const int bh = blockIdx.y;
    const int b = bh / NH;
    const int h = bh % NH;
    const size_t base = (size_t)b * T_SEQ * QKV_N;
    const int qoff = h * DH;
    const int koff = DMODEL + h * DH;
    const int voff = 2 * DMODEL + h * DH;
    const uint32_t sbase = smem_u32(sm);

    const int a_row = (lane & 15);
    const int a_coff = (lane >> 4) * 8;
    const int b_row = (lane & 7) + ((lane >> 3) & 1) * 8;
    const int b_coff = ((lane >> 4) & 1) * 8;
    const int v_krow = ((lane >> 3) & 1) * 8 + (lane & 7);
    const int v_ncol = ((lane >> 4) & 1) * 8;

    // ---- load Q tile (hi/lo) ----
    #pragma unroll
    for (int it = 0; it < 4; it++) {
        int idx = tid + it * 256;        // 0..1023
        int row = idx >> 3, g = idx & 7;
        size_t goff = base + (size_t)(qt * 128 + row) * QKV_N + qoff + g * 8;
        *(uint4*)(sm + AQH + row * LDS_PAD + g * 8) = *(const uint4*)(qkvh + goff);
        *(uint4*)(sm + AQL + row * LDS_PAD + g * 8) = *(const uint4*)(qkvl + goff);
    }

    float oacc[8][4];
    #pragma unroll
    for (int nj = 0; nj < 8; nj++)
        #pragma unroll
        for (int q = 0; q < 4; q++) oacc[nj][q] = 0.0f;
    float m_a = -1e30f, m_b = -1e30f, l_a = 0.0f, l_b = 0.0f;

    const int gr_a = qt * 128 + wid * 16 + (lane >> 2);
    const int gr_b = gr_a + 8;
    const int nkt = 2 * qt + 2;

    #pragma unroll 1
    for (int kt = 0; kt < nkt; kt++) {
        __syncthreads();
        // ---- load K/V tiles (hi/lo): 4 x (64 rows x 64 cols) ----
        {
            int r = (tid >> 3) & 31;      // helper: rows split below
        }
        #pragma unroll
        for (int it = 0; it < 8; it++) {
            int idx = tid + it * 256;     // 0..2047
            int tile = idx >> 9;          // 0:Kh 1:Kl 2:Vh 3:Vl
            int r = (idx >> 3) & 63;
            int g = idx & 7;
            const __nv_bfloat16* src = (tile & 1) ? qkvl : qkvh;
            int off = (tile < 2) ? koff : voff;
            int dsto = (tile == 0) ? AKH : (tile == 1) ? AKL : (tile == 2) ? AVH : AVL;
            *(uint4*)(sm + dsto + r * LDS_PAD + g * 8) =
                *(const uint4*)(src + base + (size_t)(kt * 64 + r) * QKV_N + off + g * 8);
        }
        __syncthreads();

        // ---- S = Qh*Kh + Ql*Kh + Qh*Kl ----
        float sacc[8][4];
        #pragma unroll
        for (int nj = 0; nj < 8; nj++)
            #pragma unroll
            for (int q = 0; q < 4; q++) sacc[nj][q] = 0.0f;

        #pragma unroll
        for (int ks = 0; ks < 4; ks++) {
            const int k0 = ks * 16;
            uint32_t qh[4], ql[4];
            ldsm_x4(qh[0], qh[1], qh[2], qh[3],
                    sbase + (AQH + (wid * 16 + a_row) * LDS_PAD + k0 + a_coff) * 2);
            ldsm_x4(ql[0], ql[1], ql[2], ql[3],
                    sbase + (AQL + (wid * 16 + a_row) * LDS_PAD + k0 + a_coff) * 2);
            uint32_t rb[4][4];
            #pragma unroll
            for (int nb = 0; nb < 4; nb++)
                ldsm_x4(rb[nb][0], rb[nb][1], rb[nb][2], rb[nb][3],
                        sbase + (AKH + (nb * 16 + b_row) * LDS_PAD + k0 + b_coff) * 2);
            #pragma unroll
            for (int nj = 0; nj < 8; nj++) {
                int nb = nj >> 1, lo = nj & 1;
                uint32_t b0 = rb[nb][lo ? 1 : 0], b1 = rb[nb][lo ? 3 : 2];
                mma_bf16(sacc[nj], qh, b0, b1);
                mma_bf16(sacc[nj], ql, b0, b1);
            }
            #pragma unroll
            for (int nb = 0; nb < 4; nb++)
                ldsm_x4(rb[nb][0], rb[nb][1], rb[nb][2], rb[nb][3],
                        sbase + (AKL + (nb * 16 + b_row) * LDS_PAD + k0 + b_coff) * 2);
            #pragma unroll
            for (int nj = 0; nj < 8; nj++) {
                int nb = nj >> 1, lo = nj & 1;
                mma_bf16(sacc[nj], qh, rb[nb][lo ? 1 : 0], rb[nb][lo ? 3 : 2]);
            }
        }

        // ---- scale + causal mask ----
        const bool diag = (kt >= 2 * qt);
        #pragma unroll
        for (int nj = 0; nj < 8; nj++) {
            #pragma unroll
            for (int q = 0; q < 4; q++) sacc[nj][q] *= 0.125f;
            if (diag) {
                int gc = kt * 64 + nj * 8 + (lane & 3) * 2;
                if (gc > gr_a)     sacc[nj][0] = -1e30f;
                if (gc + 1 > gr_a) sacc[nj][1] = -1e30f;
                if (gc > gr_b)     sacc[nj][2] = -1e30f;
                if (gc + 1 > gr_b) sacc[nj][3] = -1e30f;
            }
        }

        // ---- online softmax ----
        float mx_a = -1e30f, mx_b = -1e30f;
        #pragma unroll
        for (int nj = 0; nj < 8; nj++) {
            mx_a = fmaxf(mx_a, fmaxf(sacc[nj][0], sacc[nj][1]));
            mx_b = fmaxf(mx_b, fmaxf(sacc[nj][2], sacc[nj][3]));
        }
        mx_a = fmaxf(mx_a, __shfl_xor_sync(0xffffffffu, mx_a, 1));
        mx_a = fmaxf(mx_a, __shfl_xor_sync(0xffffffffu, mx_a, 2));
        mx_b = fmaxf(mx_b, __shfl_xor_sync(0xffffffffu, mx_b, 1));
        mx_b = fmaxf(mx_b, __shfl_xor_sync(0xffffffffu, mx_b, 2));
        float mn_a = fmaxf(m_a, mx_a), mn_b = fmaxf(m_b, mx_b);
        float corr_a = __expf(m_a - mn_a), corr_b = __expf(m_b - mn_b);
        float sum_a = 0.0f, sum_b = 0.0f;
        #pragma unroll
        for (int nj = 0; nj < 8; nj++) {
            sacc[nj][0] = __expf(sacc[nj][0] - mn_a);
            sacc[nj][1] = __expf(sacc[nj][1] - mn_a);
            sacc[nj][2] = __expf(sacc[nj][2] - mn_b);
            sacc[nj][3] = __expf(sacc[nj][3] - mn_b);
            sum_a += sacc[nj][0] + sacc[nj][1];
            sum_b += sacc[nj][2] + sacc[nj][3];
        }
        sum_a += __shfl_xor_sync(0xffffffffu, sum_a, 1);
        sum_a += __shfl_xor_sync(0xffffffffu, sum_a, 2);
        sum_b += __shfl_xor_sync(0xffffffffu, sum_b, 1);
        sum_b += __shfl_xor_sync(0xffffffffu, sum_b, 2);
        l_a = l_a * corr_a + sum_a;
        l_b = l_b * corr_b + sum_b;
        m_a = mn_a; m_b = mn_b;
        #pragma unroll
        for (int nj = 0; nj < 8; nj++) {
            oacc[nj][0] *= corr_a; oacc[nj][1] *= corr_a;
            oacc[nj][2] *= corr_b; oacc[nj][3] *= corr_b;
        }

        // ---- O += (Ph+Pl) * (Vh+Vl) : PhVh + PlVh + PhVl ----
        #pragma unroll
        for (int kb = 0; kb < 4; kb++) {
            uint32_t pa_h[4], pa_l[4];
            pack_hl(sacc[2 * kb][0], sacc[2 * kb][1], pa_h[0], pa_l[0]);
            pack_hl(sacc[2 * kb][2], sacc[2 * kb][3], pa_h[1], pa_l[1]);
            pack_hl(sacc[2 * kb + 1][0], sacc[2 * kb + 1][1], pa_h[2], pa_l[2]);
            pack_hl(sacc[2 * kb + 1][2], sacc[2 * kb + 1][3], pa_h[3], pa_l[3]);
            #pragma unroll
            for (int nout = 0; nout < 4; nout++) {
                uint32_t rv[4];
                ldsm_x4_t(rv[0], rv[1], rv[2], rv[3],
                          sbase + (AVH + (kb * 16 + v_krow) * LDS_PAD + nout * 16 + v_ncol) * 2);
                mma_bf16(oacc[2 * nout], pa_h, rv[0], rv[1]);
                mma_bf16(oacc[2 * nout], pa_l, rv[0], rv[1]);
                mma_bf16(oacc[2 * nout + 1], pa_h, rv[2], rv[3]);
                mma_bf16(oacc[2 * nout + 1], pa_l, rv[2], rv[3]);
                ldsm_x4_t(rv[0], rv[1], rv[2], rv[3],
                          sbase + (AVL + (kb * 16 + v_krow) * LDS_PAD + nout * 16 + v_ncol) * 2);
                mma_bf16(oacc[2 * nout], pa_h, rv[0], rv[1]);
                mma_bf16(oacc[2 * nout + 1], pa_h, rv[2], rv[3]);
            }
        }
    }

    // ---- epilogue: y = O / l, split hi/lo ----
    const float inv_a = 1.0f / l_a;
    const float inv_b = 1.0f / l_b;
    #pragma unroll
    for (int nj = 0; nj < 8; nj++) {
        int col = h * DH + nj * 8 + (lane & 3) * 2;
        size_t ra = (size_t)(b * T_SEQ + gr_a) * DMODEL + col;
        size_t rb2 = (size_t)(b * T_SEQ + gr_b) * DMODEL + col;
        uint32_t h0, l0, h1, l1;
        pack_hl(oacc[nj][0] * inv_a, oacc[nj][1] * inv_a, h0, l0);
        pack_hl(oacc[nj][2] * inv_b, oacc[nj][3] * inv_b, h1, l1);
        *(uint32_t*)(yh + ra) = h0;
        *(uint32_t*)(yl + ra) = l0;
        *(uint32_t*)(yh + rb2) = h1;
        *(uint32_t*)(yl + rb2) = l1;
    }
}

// ---------------------------------------------------------------------------
// fp32 -> (hi, lo) bf16 split
// ---------------------------------------------------------------------------
__global__ __launch_bounds__(256) void split_kernel(
    const float* __restrict__ in, __nv_bfloat16* __restrict__ hi,
    __nv_bfloat16* __restrict__ lo, int n4)
{
    int i = blockIdx.x * blockDim.x + threadIdx.x;
    if (i >= n4) return;
    float4 v = *(const float4*)(in + (size_t)i * 4);
    __nv_bfloat16 h[4], l[4];
    float f[4] = {v.x, v.y, v.z, v.w};
    #pragma unroll
    for (int k = 0; k < 4; ++k) {
        h[k] = __float2bfloat16(f[k]);
        l[k] = __float2bfloat16(f[k] - __bfloat162float(h[k]));
    }
    *(uint2*)(hi + (size_t)i * 4) = *(uint2*)h;
    *(uint2*)(lo + (size_t)i * 4) = *(uint2*)l;
}

// ---------------------------------------------------------------------------
// W [K,N] fp32 -> W^T (hi, lo) bf16 [N,K]
// ---------------------------------------------------------------------------
__global__ __launch_bounds__(256) void split_transpose_kernel(
    const float* __restrict__ W, __nv_bfloat16* __restrict__ hiT,
    __nv_bfloat16* __restrict__ loT, int K, int N)
{
    __shared__ float tile[32][33];
    const int tx = threadIdx.x;
    const int ty = threadIdx.y;
    const int k0 = blockIdx.y * 32;
    const int n0 = blockIdx.x * 32;
    #pragma unroll
    for (int r = 0; r < 32; r += 8)
        tile[ty + r][tx] = W[(size_t)(k0 + ty + r) * N + n0 + tx];
    __syncthreads();
    #pragma unroll
    for (int r = 0; r < 32; r += 8) {
        float v = tile[tx][ty + r];
        __nv_bfloat16 h = __float2bfloat16(v);
        __nv_bfloat16 l = __float2bfloat16(v - __bfloat162float(h));
        size_t o = (size_t)(n0 + ty + r) * K + k0 + tx;
        hiT[o] = h;
        loT[o] = l;
    }
}

// ---------------------------------------------------------------------------
extern "C" void kernel_launch(void* const* d_in, const int* in_sizes, int n_in,
                              void* d_out, int out_size)
{
    const float* x      = (const float*)d_in[0];
    const float* w_attn = (const float*)d_in[1];
    const float* b_attn = (const float*)d_in[2];
    const float* w_proj = (const float*)d_in[3];
    const float* b_proj = (const float*)d_in[4];
    float* out = (float*)d_out;

    __nv_bfloat16 *qkvh, *qkvl, *xh, *xl, *yh, *yl, *wah, *wal, *wph, *wpl;
    cudaGetSymbolAddress((void**)&qkvh, g_qkvh);
    cudaGetSymbolAddress((void**)&qkvl, g_qkvl);
    cudaGetSymbolAddress((void**)&xh, g_xh);
    cudaGetSymbolAddress((void**)&xl, g_xl);
    cudaGetSymbolAddress((void**)&yh, g_yh);
    cudaGetSymbolAddress((void**)&yl, g_yl);
    cudaGetSymbolAddress((void**)&wah, g_wah);
    cudaGetSymbolAddress((void**)&wal, g_wal);
    cudaGetSymbolAddress((void**)&wph, g_wph);
    cudaGetSymbolAddress((void**)&wpl, g_wpl);

    static bool attn_attr_set = false;
    if (!attn_attr_set) {
        cudaFuncSetAttribute(mma_attn_kernel,
                             cudaFuncAttributeMaxDynamicSharedMemorySize, ATTN_SMEM);
        attn_attr_set = true;
    }

    // 0) conversions
    {
        int n4 = (M_ROWS * DMODEL) / 4;
        split_kernel<<<(n4 + 255) / 256, 256>>>(x, xh, xl, n4);
        dim3 blk(32, 8);
        split_transpose_kernel<<<dim3(QKV_N / 32, DMODEL / 32), blk>>>(w_attn, wah, wal, DMODEL, QKV_N);
        split_transpose_kernel<<<dim3(DMODEL / 32, DMODEL / 32), blk>>>(w_proj, wph, wpl, DMODEL, DMODEL);
    }
    // 1) QKV GEMM -> bf16 hi/lo qkv
    {
        dim3 grid(QKV_N / 128, M_ROWS / 128);
        mma_gemm_kernel<<<grid, 256>>>(xh, xl, wah, wal, b_attn,
                                       nullptr, qkvh, qkvl, QKV_N);
    }
    // 2) causal flash attention on HMMA -> bf16 hi/lo y
    {
        dim3 grid(T_SEQ / 128, BATCH * NH);   // (16, 48)
        mma_attn_kernel<<<grid, 256, ATTN_SMEM>>>(qkvh, qkvl, yh, yl);
    }
    // 3) out projection -> fp32 out
    {
        dim3 grid(DMODEL / 128, M_ROWS / 128);
        mma_gemm_kernel<<<grid, 256>>>(yh, yl, wph, wpl, b_proj,
                                       out, nullptr, nullptr, DMODEL);
    }
}

// round 8
// speedup vs baseline: 2.8148x; 1.0487x over previous
#include <cuda_runtime.h>
#include <cuda_bf16.h>
#include <cstdint>
#include <math.h>

#define BATCH 4
#define T_SEQ 2048
#define NH 12
#define DMODEL 768
#define DH 64
#define M_ROWS (BATCH * T_SEQ)          // 8192
#define QKV_N (3 * DMODEL)              // 2304
#define GK DMODEL                       // GEMM K = 768
#define LDS_PAD 72                      // smem row stride in bf16 (144 B)

// ------------------------- scratch (static, allocation-free) ---------------
__device__ __nv_bfloat16 g_qkvh[(size_t)M_ROWS * QKV_N];
__device__ __nv_bfloat16 g_qkvl[(size_t)M_ROWS * QKV_N];
__device__ __nv_bfloat16 g_xh[(size_t)M_ROWS * DMODEL];
__device__ __nv_bfloat16 g_xl[(size_t)M_ROWS * DMODEL];
__device__ __nv_bfloat16 g_yh[(size_t)M_ROWS * DMODEL];
__device__ __nv_bfloat16 g_yl[(size_t)M_ROWS * DMODEL];
__device__ __nv_bfloat16 g_wah[(size_t)QKV_N * DMODEL];  // w_attn^T [2304,768]
__device__ __nv_bfloat16 g_wal[(size_t)QKV_N * DMODEL];
__device__ __nv_bfloat16 g_wph[(size_t)DMODEL * DMODEL]; // w_proj^T [768,768]
__device__ __nv_bfloat16 g_wpl[(size_t)DMODEL * DMODEL];

// ------------------------- helpers -----------------------------------------
__device__ __forceinline__ uint32_t smem_u32(const void* p) {
    uint32_t a;
    asm("{ .reg .u64 t; cvta.to.shared.u64 t, %1; cvt.u32.u64 %0, t; }" : "=r"(a) : "l"(p));
    return a;
}
__device__ __forceinline__ void cp16(uint32_t dst, const void* src) {
    asm volatile("cp.async.cg.shared.global [%0], [%1], 16;" :: "r"(dst), "l"(src));
}
#define CP_COMMIT() asm volatile("cp.async.commit_group;" ::: "memory")
#define CP_WAIT0()  asm volatile("cp.async.wait_group 0;" ::: "memory")

__device__ __forceinline__ void ldsm_x4(uint32_t& r0, uint32_t& r1,
                                        uint32_t& r2, uint32_t& r3, uint32_t addr) {
    asm volatile("ldmatrix.sync.aligned.m8n8.x4.shared.b16 {%0,%1,%2,%3}, [%4];"
                 : "=r"(r0), "=r"(r1), "=r"(r2), "=r"(r3) : "r"(addr));
}
__device__ __forceinline__ void ldsm_x4_t(uint32_t& r0, uint32_t& r1,
                                          uint32_t& r2, uint32_t& r3, uint32_t addr) {
    asm volatile("ldmatrix.sync.aligned.m8n8.x4.trans.shared.b16 {%0,%1,%2,%3}, [%4];"
                 : "=r"(r0), "=r"(r1), "=r"(r2), "=r"(r3) : "r"(addr));
}
__device__ __forceinline__ void mma_bf16(float* c, const uint32_t* a,
                                         uint32_t b0, uint32_t b1) {
    asm volatile(
        "mma.sync.aligned.m16n8k16.row.col.f32.bf16.bf16.f32 "
        "{%0,%1,%2,%3}, {%4,%5,%6,%7}, {%8,%9}, {%0,%1,%2,%3};"
        : "+f"(c[0]), "+f"(c[1]), "+f"(c[2]), "+f"(c[3])
        : "r"(a[0]), "r"(a[1]), "r"(a[2]), "r"(a[3]), "r"(b0), "r"(b1));
}
__device__ __forceinline__ void pack_hl(float f0, float f1, uint32_t& h, uint32_t& l) {
    __nv_bfloat16 h0 = __float2bfloat16(f0), h1 = __float2bfloat16(f1);
    __nv_bfloat162 hh; hh.x = h0; hh.y = h1;
    h = *(uint32_t*)&hh;
    __nv_bfloat162 ll;
    ll.x = __float2bfloat16(f0 - __bfloat162float(h0));
    ll.y = __float2bfloat16(f1 - __bfloat162float(h1));
    l = *(uint32_t*)&ll;
}

// ---------------------------------------------------------------------------
// HMMA GEMM, bf16x3 (fused single-load): C = Ah*Bh + Al*Bh + Ah*Bl + bias
// Per K-chunk (64): load Ah|Al|Bh|Bl tiles once via cp.async, run all 3 terms.
// Dynamic smem 73728 B; 256 threads = 8 warps (4M x 2N), warp 32x64.
// ---------------------------------------------------------------------------
#define GOAH 0
#define GOAL (128 * LDS_PAD)
#define GOBH (2 * 128 * LDS_PAD)
#define GOBL (3 * 128 * LDS_PAD)
#define GEMM_SMEM (4 * 128 * LDS_PAD * 2)    // 73728 bytes

__global__ __launch_bounds__(256, 2) void mma_gemm_kernel(
    const __nv_bfloat16* __restrict__ Ah, const __nv_bfloat16* __restrict__ Al,
    const __nv_bfloat16* __restrict__ Bh, const __nv_bfloat16* __restrict__ Bl,
    const float* __restrict__ bias, float* __restrict__ C,
    __nv_bfloat16* __restrict__ Ch, __nv_bfloat16* __restrict__ Cl, int N)
{
    extern __shared__ __nv_bfloat16 gsm[];
    const int tid  = threadIdx.x;
    const int wid  = tid >> 5;
    const int lane = tid & 31;
    const int m0 = blockIdx.y * 128;
    const int n0 = blockIdx.x * 128;
    const int warp_m = (wid >> 1) * 32;
    const int warp_n = (wid & 1) * 64;
    const uint32_t sbase = smem_u32(gsm);

    const int a_row = (lane & 15);
    const int a_coff = (lane >> 4) * 8;
    const int b_row = (lane & 7) + ((lane >> 3) & 1) * 8;
    const int b_coff = ((lane >> 4) & 1) * 8;

    float acc[2][8][4];
    #pragma unroll
    for (int mi = 0; mi < 2; mi++)
        #pragma unroll
        for (int nj = 0; nj < 8; nj++)
            #pragma unroll
            for (int q = 0; q < 4; q++) acc[mi][nj][q] = 0.0f;

    #pragma unroll 1
    for (int kc = 0; kc < GK; kc += 64) {
        __syncthreads();
        // load 4 tiles (128 rows x 64 cols each) via cp.async: 16 ops/thread
        #pragma unroll
        for (int it = 0; it < 16; it++) {
            int idx = tid + it * 256;          // 0..4095
            int tile = idx >> 10;              // 0:Ah 1:Al 2:Bh 3:Bl
            int rem = idx & 1023;
            int row = rem >> 3;                // 0..127
            int g   = rem & 7;                 // 16B granule
            const __nv_bfloat16* sp =
                (tile == 0) ? Ah : (tile == 1) ? Al : (tile == 2) ? Bh : Bl;
            int rbase = (tile < 2) ? m0 : n0;
            uint32_t dst = sbase + (uint32_t)(tile * 128 * LDS_PAD + row * LDS_PAD + g * 8) * 2;
            cp16(dst, sp + (size_t)(rbase + row) * GK + kc + g * 8);
        }
        CP_COMMIT();
        CP_WAIT0();
        __syncthreads();

        #pragma unroll
        for (int ks = 0; ks < 4; ks++) {
            const int k0 = ks * 16;
            uint32_t rah[2][4], ral[2][4];
            #pragma unroll
            for (int mi = 0; mi < 2; mi++) {
                uint32_t ar = (warp_m + mi * 16 + a_row) * LDS_PAD + k0 + a_coff;
                ldsm_x4(rah[mi][0], rah[mi][1], rah[mi][2], rah[mi][3],
                        sbase + (GOAH + ar) * 2);
                ldsm_x4(ral[mi][0], ral[mi][1], ral[mi][2], ral[mi][3],
                        sbase + (GOAL + ar) * 2);
            }
            #pragma unroll
            for (int nb = 0; nb < 4; nb++) {
                uint32_t br = (warp_n + nb * 16 + b_row) * LDS_PAD + k0 + b_coff;
                uint32_t rb[4];
                ldsm_x4(rb[0], rb[1], rb[2], rb[3], sbase + (GOBH + br) * 2);
                #pragma unroll
                for (int mi = 0; mi < 2; mi++)
                    #pragma unroll
                    for (int lo = 0; lo < 2; lo++) {
                        mma_bf16(acc[mi][2 * nb + lo], rah[mi], rb[lo], rb[lo + 2]);
                        mma_bf16(acc[mi][2 * nb + lo], ral[mi], rb[lo], rb[lo + 2]);
                    }
                ldsm_x4(rb[0], rb[1], rb[2], rb[3], sbase + (GOBL + br) * 2);
                #pragma unroll
                for (int mi = 0; mi < 2; mi++)
                    #pragma unroll
                    for (int lo = 0; lo < 2; lo++)
                        mma_bf16(acc[mi][2 * nb + lo], rah[mi], rb[lo], rb[lo + 2]);
            }
        }
    }

    const int mrow = m0 + warp_m + (lane >> 2);
    const int ncol = n0 + warp_n + (lane & 3) * 2;
    #pragma unroll
    for (int mi = 0; mi < 2; mi++) {
        #pragma unroll
        for (int nj = 0; nj < 8; nj++) {
            int r = mrow + mi * 16;
            int c = ncol + nj * 8;
            float bv0 = bias[c], bv1 = bias[c + 1];
            float v00 = acc[mi][nj][0] + bv0, v01 = acc[mi][nj][1] + bv1;
            float v10 = acc[mi][nj][2] + bv0, v11 = acc[mi][nj][3] + bv1;
            if (Cl) {
                uint32_t h0, l0, h1, l1;
                pack_hl(v00, v01, h0, l0);
                pack_hl(v10, v11, h1, l1);
                *(uint32_t*)(Ch + (size_t)r * N + c) = h0;
                *(uint32_t*)(Cl + (size_t)r * N + c) = l0;
                *(uint32_t*)(Ch + (size_t)(r + 8) * N + c) = h1;
                *(uint32_t*)(Cl + (size_t)(r + 8) * N + c) = l1;
            } else {
                *(float2*)(C + (size_t)r * N + c) = make_float2(v00, v01);
                *(float2*)(C + (size_t)(r + 8) * N + c) = make_float2(v10, v11);
            }
        }
    }
}

// ---------------------------------------------------------------------------
// HMMA flash attention (causal), bf16x3 S and PV, fp32 softmax/accum.
// Grid (T/128, B*NH), 256 threads = 8 warps x 16 Q-rows. K/V tiles 64 rows.
// ---------------------------------------------------------------------------
#define AQH 0
#define AQL (128 * LDS_PAD)
#define AKH (2 * 128 * LDS_PAD)
#define AKL (AKH + 64 * LDS_PAD)
#define AVH (AKL + 64 * LDS_PAD)
#define AVL (AVH + 64 * LDS_PAD)
#define ATTN_SMEM ((AVL + 64 * LDS_PAD) * 2)

__global__ __launch_bounds__(256, 2) void mma_attn_kernel(
    const __nv_bfloat16* __restrict__ qkvh, const __nv_bfloat16* __restrict__ qkvl,
    __nv_bfloat16* __restrict__ yh, __nv_bfloat16* __restrict__ yl)
{
    extern __shared__ __nv_bfloat16 sm[];
    const int tid = threadIdx.x;
    const int wid = tid >> 5;
    const int lane = tid & 31;
    const int qt = gridDim.x - 1 - blockIdx.x;     // heavy tiles first
    const int bh = blockIdx.y;
    const int b = bh / NH;
    const int h = bh % NH;
    const size_t base = (size_t)b * T_SEQ * QKV_N;
    const int qoff = h * DH;
    const int koff = DMODEL + h * DH;
    const int voff = 2 * DMODEL + h * DH;
    const uint32_t sbase = smem_u32(sm);

    const int a_row = (lane & 15);
    const int a_coff = (lane >> 4) * 8;
    const int b_row = (lane & 7) + ((lane >> 3) & 1) * 8;
    const int b_coff = ((lane >> 4) & 1) * 8;
    const int v_krow = ((lane >> 3) & 1) * 8 + (lane & 7);
    const int v_ncol = ((lane >> 4) & 1) * 8;

    // ---- load Q tile (hi/lo) via cp.async ----
    #pragma unroll
    for (int it = 0; it < 4; it++) {
        int idx = tid + it * 256;        // 0..1023
        int row = idx >> 3, g = idx & 7;
        size_t goff = base + (size_t)(qt * 128 + row) * QKV_N + qoff + g * 8;
        uint32_t so = (uint32_t)(row * LDS_PAD + g * 8) * 2;
        cp16(sbase + (AQH * 2) + so, qkvh + goff);
        cp16(sbase + (AQL * 2) + so, qkvl + goff);
    }
    CP_COMMIT();

    float oacc[8][4];
    #pragma unroll
    for (int nj = 0; nj < 8; nj++)
        #pragma unroll
        for (int q = 0; q < 4; q++) oacc[nj][q] = 0.0f;
    float m_a = -1e30f, m_b = -1e30f, l_a = 0.0f, l_b = 0.0f;

    const int gr_a = qt * 128 + wid * 16 + (lane >> 2);
    const int gr_b = gr_a + 8;
    const int nkt = 2 * qt + 2;

    #pragma unroll 1
    for (int kt = 0; kt < nkt; kt++) {
        __syncthreads();
        // ---- load K/V tiles (hi/lo) via cp.async ----
        #pragma unroll
        for (int it = 0; it < 8; it++) {
            int idx = tid + it * 256;     // 0..2047
            int tile = idx >> 9;          // 0:Kh 1:Kl 2:Vh 3:Vl
            int r = (idx >> 3) & 63;
            int g = idx & 7;
            const __nv_bfloat16* src = (tile & 1) ? qkvl : qkvh;
            int off = (tile < 2) ? koff : voff;
            int dsto = (tile == 0) ? AKH : (tile == 1) ? AKL : (tile == 2) ? AVH : AVL;
            cp16(sbase + (uint32_t)(dsto + r * LDS_PAD + g * 8) * 2,
                 src + base + (size_t)(kt * 64 + r) * QKV_N + off + g * 8);
        }
        CP_COMMIT();
        CP_WAIT0();
        __syncthreads();

        // ---- S = Qh*Kh + Ql*Kh + Qh*Kl ----
        float sacc[8][4];
        #pragma unroll
        for (int nj = 0; nj < 8; nj++)
            #pragma unroll
            for (int q = 0; q < 4; q++) sacc[nj][q] = 0.0f;

        #pragma unroll
        for (int ks = 0; ks < 4; ks++) {
            const int k0 = ks * 16;
            uint32_t qh[4], ql[4];
            ldsm_x4(qh[0], qh[1], qh[2], qh[3],
                    sbase + (AQH + (wid * 16 + a_row) * LDS_PAD + k0 + a_coff) * 2);
            ldsm_x4(ql[0], ql[1], ql[2], ql[3],
                    sbase + (AQL + (wid * 16 + a_row) * LDS_PAD + k0 + a_coff) * 2);
            #pragma unroll
            for (int nb = 0; nb < 4; nb++) {
                uint32_t br = (nb * 16 + b_row) * LDS_PAD + k0 + b_coff;
                uint32_t rb[4];
                ldsm_x4(rb[0], rb[1], rb[2], rb[3], sbase + (AKH + br) * 2);
                #pragma unroll
                for (int lo = 0; lo < 2; lo++) {
                    mma_bf16(sacc[2 * nb + lo], qh, rb[lo], rb[lo + 2]);
                    mma_bf16(sacc[2 * nb + lo], ql, rb[lo], rb[lo + 2]);
                }
                ldsm_x4(rb[0], rb[1], rb[2], rb[3], sbase + (AKL + br) * 2);
                #pragma unroll
                for (int lo = 0; lo < 2; lo++)
                    mma_bf16(sacc[2 * nb + lo], qh, rb[lo], rb[lo + 2]);
            }
        }

        // ---- scale + causal mask ----
        const bool diag = (kt >= 2 * qt);
        #pragma unroll
        for (int nj = 0; nj < 8; nj++) {
            #pragma unroll
            for (int q = 0; q < 4; q++) sacc[nj][q] *= 0.125f;
            if (diag) {
                int gc = kt * 64 + nj * 8 + (lane & 3) * 2;
                if (gc > gr_a)     sacc[nj][0] = -1e30f;
                if (gc + 1 > gr_a) sacc[nj][1] = -1e30f;
                if (gc > gr_b)     sacc[nj][2] = -1e30f;
                if (gc + 1 > gr_b) sacc[nj][3] = -1e30f;
            }
        }

        // ---- online softmax ----
        float mx_a = -1e30f, mx_b = -1e30f;
        #pragma unroll
        for (int nj = 0; nj < 8; nj++) {
            mx_a = fmaxf(mx_a, fmaxf(sacc[nj][0], sacc[nj][1]));
            mx_b = fmaxf(mx_b, fmaxf(sacc[nj][2], sacc[nj][3]));
        }
        mx_a = fmaxf(mx_a, __shfl_xor_sync(0xffffffffu, mx_a, 1));
        mx_a = fmaxf(mx_a, __shfl_xor_sync(0xffffffffu, mx_a, 2));
        mx_b = fmaxf(mx_b, __shfl_xor_sync(0xffffffffu, mx_b, 1));
        mx_b = fmaxf(mx_b, __shfl_xor_sync(0xffffffffu, mx_b, 2));
        float mn_a = fmaxf(m_a, mx_a), mn_b = fmaxf(m_b, mx_b);
        float corr_a = __expf(m_a - mn_a), corr_b = __expf(m_b - mn_b);
        float sum_a = 0.0f, sum_b = 0.0f;
        #pragma unroll
        for (int nj = 0; nj < 8; nj++) {
            sacc[nj][0] = __expf(sacc[nj][0] - mn_a);
            sacc[nj][1] = __expf(sacc[nj][1] - mn_a);
            sacc[nj][2] = __expf(sacc[nj][2] - mn_b);
            sacc[nj][3] = __expf(sacc[nj][3] - mn_b);
            sum_a += sacc[nj][0] + sacc[nj][1];
            sum_b += sacc[nj][2] + sacc[nj][3];
        }
        sum_a += __shfl_xor_sync(0xffffffffu, sum_a, 1);
        sum_a += __shfl_xor_sync(0xffffffffu, sum_a, 2);
        sum_b += __shfl_xor_sync(0xffffffffu, sum_b, 1);
        sum_b += __shfl_xor_sync(0xffffffffu, sum_b, 2);
        l_a = l_a * corr_a + sum_a;
        l_b = l_b * corr_b + sum_b;
        m_a = mn_a; m_b = mn_b;
        #pragma unroll
        for (int nj = 0; nj < 8; nj++) {
            oacc[nj][0] *= corr_a; oacc[nj][1] *= corr_a;
            oacc[nj][2] *= corr_b; oacc[nj][3] *= corr_b;
        }

        // ---- O += (Ph+Pl) * (Vh+Vl) : PhVh + PlVh + PhVl ----
        #pragma unroll
        for (int kb = 0; kb < 4; kb++) {
            uint32_t pa_h[4], pa_l[4];
            pack_hl(sacc[2 * kb][0], sacc[2 * kb][1], pa_h[0], pa_l[0]);
            pack_hl(sacc[2 * kb][2], sacc[2 * kb][3], pa_h[1], pa_l[1]);
            pack_hl(sacc[2 * kb + 1][0], sacc[2 * kb + 1][1], pa_h[2], pa_l[2]);
            pack_hl(sacc[2 * kb + 1][2], sacc[2 * kb + 1][3], pa_h[3], pa_l[3]);
            #pragma unroll
            for (int nout = 0; nout < 4; nout++) {
                uint32_t rv[4];
                ldsm_x4_t(rv[0], rv[1], rv[2], rv[3],
                          sbase + (AVH + (kb * 16 + v_krow) * LDS_PAD + nout * 16 + v_ncol) * 2);
                mma_bf16(oacc[2 * nout], pa_h, rv[0], rv[1]);
                mma_bf16(oacc[2 * nout], pa_l, rv[0], rv[1]);
                mma_bf16(oacc[2 * nout + 1], pa_h, rv[2], rv[3]);
                mma_bf16(oacc[2 * nout + 1], pa_l, rv[2], rv[3]);
                ldsm_x4_t(rv[0], rv[1], rv[2], rv[3],
                          sbase + (AVL + (kb * 16 + v_krow) * LDS_PAD + nout * 16 + v_ncol) * 2);
                mma_bf16(oacc[2 * nout], pa_h, rv[0], rv[1]);
                mma_bf16(oacc[2 * nout + 1], pa_h, rv[2], rv[3]);
            }
        }
    }

    // ---- epilogue: y = O / l, split hi/lo ----
    const float inv_a = 1.0f / l_a;
    const float inv_b = 1.0f / l_b;
    #pragma unroll
    for (int nj = 0; nj < 8; nj++) {
        int col = h * DH + nj * 8 + (lane & 3) * 2;
        size_t ra = (size_t)(b * T_SEQ + gr_a) * DMODEL + col;
        size_t rb2 = (size_t)(b * T_SEQ + gr_b) * DMODEL + col;
        uint32_t h0, l0, h1, l1;
        pack_hl(oacc[nj][0] * inv_a, oacc[nj][1] * inv_a, h0, l0);
        pack_hl(oacc[nj][2] * inv_b, oacc[nj][3] * inv_b, h1, l1);
        *(uint32_t*)(yh + ra) = h0;
        *(uint32_t*)(yl + ra) = l0;
        *(uint32_t*)(yh + rb2) = h1;
        *(uint32_t*)(yl + rb2) = l1;
    }
}

// ---------------------------------------------------------------------------
// fp32 -> (hi, lo) bf16 split
// ---------------------------------------------------------------------------
__global__ __launch_bounds__(256) void split_kernel(
    const float* __restrict__ in, __nv_bfloat16* __restrict__ hi,
    __nv_bfloat16* __restrict__ lo, int n4)
{
    int i = blockIdx.x * blockDim.x + threadIdx.x;
    if (i >= n4) return;
    float4 v = *(const float4*)(in + (size_t)i * 4);
    __nv_bfloat16 h[4], l[4];
    float f[4] = {v.x, v.y, v.z, v.w};
    #pragma unroll
    for (int k = 0; k < 4; ++k) {
        h[k] = __float2bfloat16(f[k]);
        l[k] = __float2bfloat16(f[k] - __bfloat162float(h[k]));
    }
    *(uint2*)(hi + (size_t)i * 4) = *(uint2*)h;
    *(uint2*)(lo + (size_t)i * 4) = *(uint2*)l;
}

// ---------------------------------------------------------------------------
// W [K,N] fp32 -> W^T (hi, lo) bf16 [N,K]
// ---------------------------------------------------------------------------
__global__ __launch_bounds__(256) void split_transpose_kernel(
    const float* __restrict__ W, __nv_bfloat16* __restrict__ hiT,
    __nv_bfloat16* __restrict__ loT, int K, int N)
{
    __shared__ float tile[32][33];
    const int tx = threadIdx.x;
    const int ty = threadIdx.y;
    const int k0 = blockIdx.y * 32;
    const int n0 = blockIdx.x * 32;
    #pragma unroll
    for (int r = 0; r < 32; r += 8)
        tile[ty + r][tx] = W[(size_t)(k0 + ty + r) * N + n0 + tx];
    __syncthreads();
    #pragma unroll
    for (int r = 0; r < 32; r += 8) {
        float v = tile[tx][ty + r];
        __nv_bfloat16 h = __float2bfloat16(v);
        __nv_bfloat16 l = __float2bfloat16(v - __bfloat162float(h));
        size_t o = (size_t)(n0 + ty + r) * K + k0 + tx;
        hiT[o] = h;
        loT[o] = l;
    }
}

// ---------------------------------------------------------------------------
extern "C" void kernel_launch(void* const* d_in, const int* in_sizes, int n_in,
                              void* d_out, int out_size)
{
    const float* x      = (const float*)d_in[0];
    const float* w_attn = (const float*)d_in[1];
    const float* b_attn = (const float*)d_in[2];
    const float* w_proj = (const float*)d_in[3];
    const float* b_proj = (const float*)d_in[4];
    float* out = (float*)d_out;

    __nv_bfloat16 *qkvh, *qkvl, *xh, *xl, *yh, *yl, *wah, *wal, *wph, *wpl;
    cudaGetSymbolAddress((void**)&qkvh, g_qkvh);
    cudaGetSymbolAddress((void**)&qkvl, g_qkvl);
    cudaGetSymbolAddress((void**)&xh, g_xh);
    cudaGetSymbolAddress((void**)&xl, g_xl);
    cudaGetSymbolAddress((void**)&yh, g_yh);
    cudaGetSymbolAddress((void**)&yl, g_yl);
    cudaGetSymbolAddress((void**)&wah, g_wah);
    cudaGetSymbolAddress((void**)&wal, g_wal);
    cudaGetSymbolAddress((void**)&wph, g_wph);
    cudaGetSymbolAddress((void**)&wpl, g_wpl);

    static bool attr_set = false;
    if (!attr_set) {
        cudaFuncSetAttribute(mma_attn_kernel,
                             cudaFuncAttributeMaxDynamicSharedMemorySize, ATTN_SMEM);
        cudaFuncSetAttribute(mma_gemm_kernel,
                             cudaFuncAttributeMaxDynamicSharedMemorySize, GEMM_SMEM);
        attr_set = true;
    }

    // 0) conversions
    {
        int n4 = (M_ROWS * DMODEL) / 4;
        split_kernel<<<(n4 + 255) / 256, 256>>>(x, xh, xl, n4);
        dim3 blk(32, 8);
        split_transpose_kernel<<<dim3(QKV_N / 32, DMODEL / 32), blk>>>(w_attn, wah, wal, DMODEL, QKV_N);
        split_transpose_kernel<<<dim3(DMODEL / 32, DMODEL / 32), blk>>>(w_proj, wph, wpl, DMODEL, DMODEL);
    }
    // 1) QKV GEMM -> bf16 hi/lo qkv
    {
        dim3 grid(QKV_N / 128, M_ROWS / 128);
        mma_gemm_kernel<<<grid, 256, GEMM_SMEM>>>(xh, xl, wah, wal, b_attn,
                                                  nullptr, qkvh, qkvl, QKV_N);
    }
    // 2) causal flash attention on HMMA -> bf16 hi/lo y
    {
        dim3 grid(T_SEQ / 128, BATCH * NH);   // (16, 48)
        mma_attn_kernel<<<grid, 256, ATTN_SMEM>>>(qkvh, qkvl, yh, yl);
    }
    // 3) out projection -> fp32 out
    {
        dim3 grid(DMODEL / 128, M_ROWS / 128);
        mma_gemm_kernel<<<grid, 256, GEMM_SMEM>>>(yh, yl, wph, wpl, b_proj,
                                                  out, nullptr, nullptr, DMODEL);
    }
}